// round 3
// baseline (speedup 1.0000x reference)
#include <cuda_runtime.h>
#include <math.h>

// ---------------------------------------------------------------------------
// NNGAT_Net: B=512 graphs, N=200 nodes, INDIM=200.
// GAT1(200->32) -> topk(100) -> [bool augment-adj] -> GAT2(32->32) -> topk(50)
// -> readouts -> 3-layer MLP -> log_softmax.
// One CTA per batch, 256 threads, 64.3KB smem => 3 CTAs/SM.
// Weights read via __ldg (L1-broadcast across CTAs). GAT1 alphas in registers
// (shuffle-fed sparse aggregation); GAT2 dense with smem alpha scratch.
// Output layout: logp [512*2] | s1 [512*100] | s2 [512*50]
// ---------------------------------------------------------------------------

namespace {
constexpr int N_    = 200;
constexpr int IND   = 200;
constexpr int D1_   = 32;
constexpr int D2_   = 32;
constexpr int K1_   = 100;
constexpr int K2_   = 50;
constexpr int NT    = 256;
constexpr float NEGF = -1e9f;

// shared memory layout (float indices)
constexpr int OFF_H     = 0;        // 6400: h1 [200x32]; later xk[100x32]@+0, xk2[50x32]@+3200
constexpr int OFF_HO    = 6400;     // 6400: hout1 [200x32]; later sH2[100x32]@+0, sOUT2@+3200
constexpr int OFF_ES    = 12800;    // 200
constexpr int OFF_ED    = 13000;    // 200
constexpr int OFF_SC    = 13200;    // 200
constexpr int OFF_VAL   = 13400;    // 100
constexpr int OFF_PERM  = 13500;    // 100 (int)
constexpr int OFF_PERM2 = 13600;    // 50  (int)
constexpr int OFF_ADJB  = 13652;    // 1400 (u32): adj bitset [200][7]; later GAT2 alpha scratch [8x100]
constexpr int OFF_AKB   = 15052;    // 400 (u32): pooled adj bitset [100][4]
constexpr int OFF_A2B   = 15452;    // 400 (u32): augmented adj bitset [100][4]
constexpr int OFF_Z     = 15852;    // 192: z[128], z1[32], z2[8], logits
constexpr int OFF_RED   = 16044;    // 32
constexpr int SMEM_FLOATS = 16076;  // 64304 bytes -> 3 CTAs/SM
}

__device__ __forceinline__ float warpMax(float v) {
    #pragma unroll
    for (int o = 16; o > 0; o >>= 1) v = fmaxf(v, __shfl_xor_sync(0xffffffffu, v, o));
    return v;
}
__device__ __forceinline__ float warpSum(float v) {
    #pragma unroll
    for (int o = 16; o > 0; o >>= 1) v += __shfl_xor_sync(0xffffffffu, v, o);
    return v;
}
__device__ __forceinline__ float lrelu02(float x) { return x > 0.f ? x : 0.2f * x; }

__global__ __launch_bounds__(NT, 3)
void nngat_kernel(
    const float* __restrict__ x,     const float* __restrict__ adj,
    const float* __restrict__ W1,    const float* __restrict__ a1s,
    const float* __restrict__ a1d,   const float* __restrict__ b1,
    const float* __restrict__ W2,    const float* __restrict__ a2s,
    const float* __restrict__ a2d,   const float* __restrict__ b2,
    const float* __restrict__ pw1,   const float* __restrict__ pw2,
    const float* __restrict__ fc1_w, const float* __restrict__ fc1_b,
    const float* __restrict__ fc2_w, const float* __restrict__ fc2_b,
    const float* __restrict__ fc3_w, const float* __restrict__ fc3_b,
    const float* __restrict__ bn4_g, const float* __restrict__ bn4_b,
    const float* __restrict__ bn5_g, const float* __restrict__ bn5_b,
    float* __restrict__ out)
{
    extern __shared__ float sm[];
    int*      smi = (int*)sm;
    unsigned* smu = (unsigned*)sm;

    const int b    = blockIdx.x;
    const int tid  = threadIdx.x;
    const int lane = tid & 31;
    const int wid  = tid >> 5;

    const float* xb   = x   + (size_t)b * N_ * IND;
    const float* adjb = adj + (size_t)b * N_ * N_;

    // ---- norms of pw1/pw2 ----
    if (wid == 0) {
        float v = pw1[lane];
        float s = warpSum(v * v);
        if (lane == 0) sm[OFF_RED + 0] = sqrtf(s) + 1e-16f;
    }
    if (wid == 1) {
        float v = pw2[lane];
        float s = warpSum(v * v);
        if (lane == 0) sm[OFF_RED + 1] = sqrtf(s) + 1e-16f;
    }

    const float a1s_l = __ldg(&a1s[lane]);
    const float a1d_l = __ldg(&a1d[lane]);
    const float b1_l  = __ldg(&b1[lane]);

    // ============ Phase A: h = x @ W1 ; es = h.a1s ; ed = h.a1d =============
    // Warp owns rows [wid*25, wid*25+25), 5 at a time; W1 read via __ldg
    // (identical across CTAs -> L1 broadcast hits).
    {
        const int rbase = wid * 25;
        #pragma unroll
        for (int g = 0; g < 5; g++) {
            const int ib = rbase + g * 5;
            const float4* xp0 = (const float4*)(xb + (ib + 0) * IND);
            const float4* xp1 = (const float4*)(xb + (ib + 1) * IND);
            const float4* xp2 = (const float4*)(xb + (ib + 2) * IND);
            const float4* xp3 = (const float4*)(xb + (ib + 3) * IND);
            const float4* xp4 = (const float4*)(xb + (ib + 4) * IND);
            float a0 = 0.f, a1 = 0.f, a2 = 0.f, a3 = 0.f, a4 = 0.f;
            #pragma unroll 2
            for (int k4 = 0; k4 < IND / 4; k4++) {
                float4 v0 = __ldg(xp0 + k4);
                float4 v1 = __ldg(xp1 + k4);
                float4 v2 = __ldg(xp2 + k4);
                float4 v3 = __ldg(xp3 + k4);
                float4 v4 = __ldg(xp4 + k4);
                const int k = k4 * 4;
                float w0 = __ldg(&W1[(k + 0) * D1_ + lane]);
                float w1 = __ldg(&W1[(k + 1) * D1_ + lane]);
                float w2 = __ldg(&W1[(k + 2) * D1_ + lane]);
                float w3 = __ldg(&W1[(k + 3) * D1_ + lane]);
                a0 = fmaf(v0.x, w0, fmaf(v0.y, w1, fmaf(v0.z, w2, fmaf(v0.w, w3, a0))));
                a1 = fmaf(v1.x, w0, fmaf(v1.y, w1, fmaf(v1.z, w2, fmaf(v1.w, w3, a1))));
                a2 = fmaf(v2.x, w0, fmaf(v2.y, w1, fmaf(v2.z, w2, fmaf(v2.w, w3, a2))));
                a3 = fmaf(v3.x, w0, fmaf(v3.y, w1, fmaf(v3.z, w2, fmaf(v3.w, w3, a3))));
                a4 = fmaf(v4.x, w0, fmaf(v4.y, w1, fmaf(v4.z, w2, fmaf(v4.w, w3, a4))));
            }
            float hr[5] = {a0, a1, a2, a3, a4};
            #pragma unroll
            for (int r = 0; r < 5; r++) {
                sm[OFF_H + (ib + r) * D1_ + lane] = hr[r];
                float es = warpSum(hr[r] * a1s_l);
                float ed = warpSum(hr[r] * a1d_l);
                if (lane == 0) { sm[OFF_ES + ib + r] = es; sm[OFF_ED + ib + r] = ed; }
            }
        }
    }
    __syncthreads();

    // ============ Phase B: GAT1 softmax + sparse shuffle aggregation ========
    for (int i0 = 0; i0 < N_; i0 += 8) {
        const int i = i0 + wid;
        const float edi = sm[OFF_ED + i];

        unsigned mw[7];
        float al[7];
        float mx = -INFINITY;
        #pragma unroll
        for (int c = 0; c < 7; c++) {
            const int j = c * 32 + lane;
            float w = (j < N_) ? adjb[i * N_ + j] : 0.f;
            unsigned bal = __ballot_sync(0xffffffffu, w > 0.f);
            if (lane == 0) smu[OFF_ADJB + i * 7 + c] = bal;   // pure adjacency bitset
            if ((i >> 5) == c) bal |= 1u << (i & 31);         // self-loop
            mw[c] = bal;
            float lg = NEGF;
            if ((bal >> lane) & 1u) lg = lrelu02(edi + sm[OFF_ES + j]);
            al[c] = lg;
            mx = fmaxf(mx, lg);
        }
        mx = warpMax(mx);

        float s = 0.f;
        #pragma unroll
        for (int c = 0; c < 7; c++) {
            float e = __expf(al[c] - mx);   // masked lanes: exp(-1e9) -> 0
            al[c] = e;
            s += e;
        }
        s = warpSum(s);
        const float inv = __fdividef(1.f, s);

        float acc0 = 0.f, acc1 = 0.f;
        #pragma unroll
        for (int c = 0; c < 7; c++) {
            unsigned w = mw[c];               // warp-uniform
            const float* hb = sm + OFF_H + c * 32 * D1_ + lane;
            while (w) {
                const int t = __ffs(w) - 1; w &= w - 1;
                float a = __shfl_sync(0xffffffffu, al[c], t);
                acc0 = fmaf(a, hb[t * D1_], acc0);
                if (w) {
                    const int t2 = __ffs(w) - 1; w &= w - 1;
                    float a2v = __shfl_sync(0xffffffffu, al[c], t2);
                    acc1 = fmaf(a2v, hb[t2 * D1_], acc1);
                }
            }
        }
        sm[OFF_HO + i * D1_ + lane] = (acc0 + acc1) * inv + b1_l;
    }
    __syncthreads();

    // ============ Phase C: pool-1 ===========================================
    {
        const float pw1_l = __ldg(&pw1[lane]);
        const float invn1 = __fdividef(1.f, sm[OFF_RED + 0]);
        for (int i0 = 0; i0 < N_; i0 += 8) {
            const int i = i0 + wid;
            float s = warpSum(sm[OFF_HO + i * D1_ + lane] * pw1_l);
            if (lane == 0) sm[OFF_SC + i] = __fdividef(1.f, 1.f + __expf(-s * invn1));
        }
    }
    __syncthreads();

    // stable descending rank == jax.lax.top_k order
    if (tid < N_) {
        const float si = sm[OFF_SC + tid];
        int cnt = 0;
        for (int j = 0; j < N_; j++) {
            const float sj = sm[OFF_SC + j];
            cnt += (sj > si) || (sj == si && j < tid);
        }
        if (cnt < K1_) smi[OFF_PERM + cnt] = tid;
    }
    __syncthreads();

    for (int r = tid; r < K1_; r += NT) {
        float v = sm[OFF_SC + smi[OFF_PERM + r]];
        sm[OFF_VAL + r] = v;
        out[512 * 2 + (size_t)b * K1_ + r] = v;
    }
    __syncthreads();

    // gated xk = hout[perm] * vals  (into dead h1 region)
    for (int t = tid; t < K1_ * D1_; t += NT) {
        const int r = t >> 5, d = t & 31;
        sm[OFF_H + t] = sm[OFF_HO + smi[OFF_PERM + r] * D1_ + d] * sm[OFF_VAL + r];
    }
    __syncthreads();

    // x1 readout (warp0)
    if (tid < 32) {
        float mx = -INFINITY, s = 0.f;
        for (int r = 0; r < K1_; r++) {
            float v = sm[OFF_H + r * D1_ + tid];
            mx = fmaxf(mx, v);
            s += v;
        }
        sm[OFF_Z + tid]      = mx;
        sm[OFF_Z + 32 + tid] = s * (1.f / K1_);
    }
    // AKB: pooled adjacency bitset from smem ADJB
    for (int t = tid; t < K1_ * 4; t += NT) {
        const int r = t >> 2, w = t & 3;
        const int pr = smi[OFF_PERM + r];
        unsigned bits = 0;
        const int cmax = min(w * 32 + 32, K1_);
        for (int c = w * 32; c < cmax; c++) {
            const int pc = smi[OFF_PERM + c];
            if ((smu[OFF_ADJB + pr * 7 + (pc >> 5)] >> (pc & 31)) & 1u)
                bits |= 1u << (c - w * 32);
        }
        smu[OFF_AKB + t] = bits;
    }
    __syncthreads();

    // a2 = ak | (ak_nz @ ak_nz)   (sparse: iterate set bits of ak row)
    for (int t = tid; t < K1_ * 4; t += NT) {
        const int r = t >> 2, w = t & 3;
        unsigned acc = smu[OFF_AKB + t];
        #pragma unroll
        for (int kc = 0; kc < 4; kc++) {
            unsigned rw = smu[OFF_AKB + r * 4 + kc];
            while (rw) {
                const int k = __ffs(rw) - 1; rw &= rw - 1;
                acc |= smu[OFF_AKB + (kc * 32 + k) * 4 + w];
            }
        }
        smu[OFF_A2B + t] = acc;
    }
    __syncthreads();

    // ============ Phase E: GAT2 =============================================
    const float a2s_l = __ldg(&a2s[lane]);
    const float a2d_l = __ldg(&a2d[lane]);
    const float b2_l  = __ldg(&b2[lane]);
    float* sXK   = sm + OFF_H;                 // [100x32] pooled features
    float* sH2   = sm + OFF_HO;                // [100x32]
    float* sOUT2 = sm + OFF_HO + K1_ * D2_;    // [100x32]
    float* sAL2  = sm + OFF_ADJB;              // ADJB dead -> [8x100] alpha scratch

    for (int i0 = 0; i0 < K1_; i0 += 8) {
        const int i = i0 + wid;
        if (i < K1_) {
            const float4* xr4 = (const float4*)(sXK + i * D1_);
            float acc = 0.f;
            #pragma unroll
            for (int k4 = 0; k4 < D1_ / 4; k4++) {
                float4 xv = xr4[k4];
                const int k = k4 * 4;
                acc = fmaf(xv.x, __ldg(&W2[(k + 0) * D2_ + lane]), acc);
                acc = fmaf(xv.y, __ldg(&W2[(k + 1) * D2_ + lane]), acc);
                acc = fmaf(xv.z, __ldg(&W2[(k + 2) * D2_ + lane]), acc);
                acc = fmaf(xv.w, __ldg(&W2[(k + 3) * D2_ + lane]), acc);
            }
            sH2[i * D2_ + lane] = acc;
            float es = warpSum(acc * a2s_l);
            float ed = warpSum(acc * a2d_l);
            if (lane == 0) { sm[OFF_ES + i] = es; sm[OFF_ED + i] = ed; }
        }
    }
    __syncthreads();

    for (int i0 = 0; i0 < K1_; i0 += 8) {
        const int i = i0 + wid;
        if (i < K1_) {
            const float edi = sm[OFF_ED + i];
            float* al2 = sAL2 + wid * K1_;
            float alr[4];
            float mx = -INFINITY;
            #pragma unroll
            for (int c = 0; c < 4; c++) {
                const int j = c * 32 + lane;
                float lg = NEGF;
                if (j < K1_) {
                    bool msk = (j == i) || ((smu[OFF_A2B + i * 4 + c] >> lane) & 1u);
                    if (msk) lg = lrelu02(edi + sm[OFF_ES + j]);
                }
                alr[c] = lg;
                mx = fmaxf(mx, lg);
            }
            mx = warpMax(mx);
            float sme = 0.f;
            #pragma unroll
            for (int c = 0; c < 4; c++) {
                const int j = c * 32 + lane;
                if (j < K1_) {
                    float e = __expf(alr[c] - mx);
                    al2[j] = e;
                    sme += e;
                }
            }
            sme = warpSum(sme);
            const float inv = __fdividef(1.f, sme);

            const float4* al4 = (const float4*)al2;
            float acc0 = 0.f, acc1 = 0.f, acc2 = 0.f, acc3 = 0.f;
            #pragma unroll 5
            for (int j4 = 0; j4 < K1_ / 4; j4++) {
                float4 a = al4[j4];
                const int j = j4 * 4;
                acc0 = fmaf(a.x, sH2[(j + 0) * D2_ + lane], acc0);
                acc1 = fmaf(a.y, sH2[(j + 1) * D2_ + lane], acc1);
                acc2 = fmaf(a.z, sH2[(j + 2) * D2_ + lane], acc2);
                acc3 = fmaf(a.w, sH2[(j + 3) * D2_ + lane], acc3);
            }
            sOUT2[i * D2_ + lane] = ((acc0 + acc1) + (acc2 + acc3)) * inv + b2_l;
        }
    }
    __syncthreads();

    // ============ Phase F: pool-2 ===========================================
    {
        const float pw2_l = __ldg(&pw2[lane]);
        const float invn2 = __fdividef(1.f, sm[OFF_RED + 1]);
        for (int i0 = 0; i0 < K1_; i0 += 8) {
            const int i = i0 + wid;
            if (i < K1_) {
                float s = warpSum(sOUT2[i * D2_ + lane] * pw2_l);
                if (lane == 0) sm[OFF_SC + i] = __fdividef(1.f, 1.f + __expf(-s * invn2));
            }
        }
    }
    __syncthreads();

    if (tid < K1_) {
        const float si = sm[OFF_SC + tid];
        int cnt = 0;
        for (int j = 0; j < K1_; j++) {
            const float sj = sm[OFF_SC + j];
            cnt += (sj > si) || (sj == si && j < tid);
        }
        if (cnt < K2_) smi[OFF_PERM2 + cnt] = tid;
    }
    __syncthreads();

    for (int r = tid; r < K2_; r += NT) {
        float v = sm[OFF_SC + smi[OFF_PERM2 + r]];
        sm[OFF_VAL + r] = v;
        out[512 * 2 + 512 * K1_ + (size_t)b * K2_ + r] = v;
    }
    __syncthreads();

    float* sXK2 = sm + OFF_H + K1_ * D1_;   // [50x32]
    for (int t = tid; t < K2_ * D2_; t += NT) {
        const int r = t >> 5, d = t & 31;
        sXK2[t] = sOUT2[smi[OFF_PERM2 + r] * D2_ + d] * sm[OFF_VAL + r];
    }
    __syncthreads();

    if (tid < 32) {
        float mx = -INFINITY, s = 0.f;
        for (int r = 0; r < K2_; r++) {
            float v = sXK2[r * D2_ + tid];
            mx = fmaxf(mx, v);
            s += v;
        }
        sm[OFF_Z + 64 + tid] = mx;
        sm[OFF_Z + 96 + tid] = s * (1.f / K2_);
    }
    __syncthreads();

    // ============ Phase G: MLP head (warp 0) ================================
    if (wid == 0) {
        const float invbn = 1.0f / sqrtf(1.0f + 1e-5f);
        float acc = __ldg(&fc1_b[lane]);
        #pragma unroll 4
        for (int k = 0; k < 128; k++) acc = fmaf(sm[OFF_Z + k], __ldg(&fc1_w[k * 32 + lane]), acc);
        acc = fmaxf(acc, 0.f);
        sm[OFF_Z + 128 + lane] = __ldg(&bn4_g[lane]) * acc * invbn + __ldg(&bn4_b[lane]);
        __syncwarp();
        if (lane < 8) {
            float a = __ldg(&fc2_b[lane]);
            #pragma unroll
            for (int k = 0; k < 32; k++) a = fmaf(sm[OFF_Z + 128 + k], __ldg(&fc2_w[k * 8 + lane]), a);
            a = fmaxf(a, 0.f);
            sm[OFF_Z + 160 + lane] = __ldg(&bn5_g[lane]) * a * invbn + __ldg(&bn5_b[lane]);
        }
        __syncwarp();
        if (lane < 2) {
            float a = __ldg(&fc3_b[lane]);
            #pragma unroll
            for (int k = 0; k < 8; k++) a = fmaf(sm[OFF_Z + 160 + k], __ldg(&fc3_w[k * 2 + lane]), a);
            sm[OFF_Z + 170 + lane] = a;
        }
        __syncwarp();
        if (lane == 0) {
            float l0 = sm[OFF_Z + 170], l1 = sm[OFF_Z + 171];
            float m = fmaxf(l0, l1);
            float lse = m + __logf(__expf(l0 - m) + __expf(l1 - m));
            out[(size_t)b * 2 + 0] = l0 - lse;
            out[(size_t)b * 2 + 1] = l1 - lse;
        }
    }
}

extern "C" void kernel_launch(void* const* d_in, const int* in_sizes, int n_in,
                              void* d_out, int out_size) {
    const float* x     = (const float*)d_in[0];
    const float* adj   = (const float*)d_in[1];
    const float* W1    = (const float*)d_in[2];
    const float* a1s   = (const float*)d_in[3];
    const float* a1d   = (const float*)d_in[4];
    const float* b1    = (const float*)d_in[5];
    const float* W2    = (const float*)d_in[6];
    const float* a2s   = (const float*)d_in[7];
    const float* a2d   = (const float*)d_in[8];
    const float* b2    = (const float*)d_in[9];
    const float* pw1   = (const float*)d_in[10];
    const float* pw2   = (const float*)d_in[11];
    const float* fc1w  = (const float*)d_in[12];
    const float* fc1b  = (const float*)d_in[13];
    const float* fc2w  = (const float*)d_in[14];
    const float* fc2b  = (const float*)d_in[15];
    const float* fc3w  = (const float*)d_in[16];
    const float* fc3b  = (const float*)d_in[17];
    const float* bn4g  = (const float*)d_in[18];
    const float* bn4b  = (const float*)d_in[19];
    const float* bn5g  = (const float*)d_in[20];
    const float* bn5b  = (const float*)d_in[21];
    float* out = (float*)d_out;

    const int smem_bytes = SMEM_FLOATS * (int)sizeof(float);
    cudaFuncSetAttribute(nngat_kernel, cudaFuncAttributeMaxDynamicSharedMemorySize,
                         smem_bytes);

    nngat_kernel<<<512, NT, smem_bytes>>>(
        x, adj, W1, a1s, a1d, b1, W2, a2s, a2d, b2, pw1, pw2,
        fc1w, fc1b, fc2w, fc2b, fc3w, fc3b, bn4g, bn4b, bn5g, bn5b, out);
}

// round 5
// speedup vs baseline: 1.0861x; 1.0861x over previous
#include <cuda_runtime.h>
#include <math.h>

// ---------------------------------------------------------------------------
// NNGAT_Net: B=512, N=200, INDIM=200.
// One CTA per batch, 256 threads, 71.5KB smem => 3 CTAs/SM.
// W1 staged in dead HO region (Phase A only); W2 staged in dead ADJB region.
// GAT1: ballot bitset + padded smem alpha rows (224/warp) + sparse __ffs
// LDS-fed aggregation. Output: logp [512*2] | s1 [512*100] | s2 [512*50]
// ---------------------------------------------------------------------------

namespace {
constexpr int N_    = 200;
constexpr int IND   = 200;
constexpr int D1_   = 32;
constexpr int D2_   = 32;
constexpr int K1_   = 100;
constexpr int K2_   = 50;
constexpr int NT    = 256;
constexpr int ALP   = 224;          // padded alpha row (7*32) -- OOB-safe stores
constexpr float NEGF = -1e9f;

// shared memory layout (float indices)
constexpr int OFF_H     = 0;        // 6400: h1 [200x32]; later xk[100x32]@+0, xk2[50x32]@+3200
constexpr int OFF_HO    = 6400;     // 6400: W1 staged (Phase A) -> hout1 [200x32] -> sH2/sOUT2
constexpr int OFF_AL    = 12800;    // 1792: per-warp alpha rows [8x224]; GAT2 scratch [8x100]
constexpr int OFF_ES    = 14592;    // 200
constexpr int OFF_ED    = 14792;    // 200
constexpr int OFF_SC    = 14992;    // 200
constexpr int OFF_VAL   = 15192;    // 100
constexpr int OFF_PERM  = 15292;    // 100 (int)
constexpr int OFF_PERM2 = 15392;    // 52  (int)
constexpr int OFF_ADJB  = 15444;    // 1400 (u32): adj bitset [200][7]; later W2 [32x32]
constexpr int OFF_AKB   = 16844;    // 400 (u32): pooled adj bitset [100][4]
constexpr int OFF_A2B   = 17244;    // 400 (u32): augmented adj bitset [100][4]
constexpr int OFF_Z     = 17644;    // 192
constexpr int OFF_RED   = 17836;    // 32
constexpr int SMEM_FLOATS = 17868;  // 71472 bytes -> 3 CTAs/SM
}

__device__ __forceinline__ float warpMax(float v) {
    #pragma unroll
    for (int o = 16; o > 0; o >>= 1) v = fmaxf(v, __shfl_xor_sync(0xffffffffu, v, o));
    return v;
}
__device__ __forceinline__ float warpSum(float v) {
    #pragma unroll
    for (int o = 16; o > 0; o >>= 1) v += __shfl_xor_sync(0xffffffffu, v, o);
    return v;
}
__device__ __forceinline__ float lrelu02(float x) { return x > 0.f ? x : 0.2f * x; }

__global__ __launch_bounds__(NT, 3)
void nngat_kernel(
    const float* __restrict__ x,     const float* __restrict__ adj,
    const float* __restrict__ W1,    const float* __restrict__ a1s,
    const float* __restrict__ a1d,   const float* __restrict__ b1,
    const float* __restrict__ W2,    const float* __restrict__ a2s,
    const float* __restrict__ a2d,   const float* __restrict__ b2,
    const float* __restrict__ pw1,   const float* __restrict__ pw2,
    const float* __restrict__ fc1_w, const float* __restrict__ fc1_b,
    const float* __restrict__ fc2_w, const float* __restrict__ fc2_b,
    const float* __restrict__ fc3_w, const float* __restrict__ fc3_b,
    const float* __restrict__ bn4_g, const float* __restrict__ bn4_b,
    const float* __restrict__ bn5_g, const float* __restrict__ bn5_b,
    float* __restrict__ out)
{
    extern __shared__ float sm[];
    int*      smi = (int*)sm;
    unsigned* smu = (unsigned*)sm;

    const int b    = blockIdx.x;
    const int tid  = threadIdx.x;
    const int lane = tid & 31;
    const int wid  = tid >> 5;

    const float* xb   = x   + (size_t)b * N_ * IND;
    const float* adjb = adj + (size_t)b * N_ * N_;

    // ---- stage W1 into (currently dead) HO region; pw norms ----
    {
        const float4* w4 = (const float4*)W1;
        float4* d4 = (float4*)(sm + OFF_HO);
        for (int t = tid; t < IND * D1_ / 4; t += NT) d4[t] = w4[t];
    }
    if (wid == 0) {
        float v = pw1[lane];
        float s = warpSum(v * v);
        if (lane == 0) sm[OFF_RED + 0] = sqrtf(s) + 1e-16f;
    }
    if (wid == 1) {
        float v = pw2[lane];
        float s = warpSum(v * v);
        if (lane == 0) sm[OFF_RED + 1] = sqrtf(s) + 1e-16f;
    }
    __syncthreads();

    const float a1s_l = __ldg(&a1s[lane]);
    const float a1d_l = __ldg(&a1d[lane]);
    const float b1_l  = __ldg(&b1[lane]);

    // ============ Phase A: h = x @ W1 ; es/ed ===============================
    {
        const float* sW = sm + OFF_HO;
        const int rbase = wid * 25;
        #pragma unroll
        for (int g = 0; g < 5; g++) {
            const int ib = rbase + g * 5;
            const float4* xp0 = (const float4*)(xb + (ib + 0) * IND);
            const float4* xp1 = (const float4*)(xb + (ib + 1) * IND);
            const float4* xp2 = (const float4*)(xb + (ib + 2) * IND);
            const float4* xp3 = (const float4*)(xb + (ib + 3) * IND);
            const float4* xp4 = (const float4*)(xb + (ib + 4) * IND);
            float a0 = 0.f, a1 = 0.f, a2 = 0.f, a3 = 0.f, a4 = 0.f;
            #pragma unroll 2
            for (int k4 = 0; k4 < IND / 4; k4++) {
                float4 v0 = __ldg(xp0 + k4);
                float4 v1 = __ldg(xp1 + k4);
                float4 v2 = __ldg(xp2 + k4);
                float4 v3 = __ldg(xp3 + k4);
                float4 v4 = __ldg(xp4 + k4);
                const int k = k4 * 4;
                float w0 = sW[(k + 0) * D1_ + lane];
                float w1 = sW[(k + 1) * D1_ + lane];
                float w2 = sW[(k + 2) * D1_ + lane];
                float w3 = sW[(k + 3) * D1_ + lane];
                a0 = fmaf(v0.x, w0, fmaf(v0.y, w1, fmaf(v0.z, w2, fmaf(v0.w, w3, a0))));
                a1 = fmaf(v1.x, w0, fmaf(v1.y, w1, fmaf(v1.z, w2, fmaf(v1.w, w3, a1))));
                a2 = fmaf(v2.x, w0, fmaf(v2.y, w1, fmaf(v2.z, w2, fmaf(v2.w, w3, a2))));
                a3 = fmaf(v3.x, w0, fmaf(v3.y, w1, fmaf(v3.z, w2, fmaf(v3.w, w3, a3))));
                a4 = fmaf(v4.x, w0, fmaf(v4.y, w1, fmaf(v4.z, w2, fmaf(v4.w, w3, a4))));
            }
            float hr[5] = {a0, a1, a2, a3, a4};
            #pragma unroll
            for (int r = 0; r < 5; r++) {
                sm[OFF_H + (ib + r) * D1_ + lane] = hr[r];
                float es = warpSum(hr[r] * a1s_l);
                float ed = warpSum(hr[r] * a1d_l);
                if (lane == 0) { sm[OFF_ES + ib + r] = es; sm[OFF_ED + ib + r] = ed; }
            }
        }
    }
    __syncthreads();   // W1 staging dead from here; HO becomes hout1

    // ============ Phase B: GAT1 softmax + sparse smem aggregation ===========
    for (int i0 = 0; i0 < N_; i0 += 8) {
        const int i = i0 + wid;
        const float edi = sm[OFF_ED + i];
        float* al = sm + OFF_AL + wid * ALP;   // padded row: stores to [0,224) safe

        unsigned mw[7];
        float alr[7];
        float mx = -INFINITY;
        #pragma unroll
        for (int c = 0; c < 7; c++) {
            const int j = c * 32 + lane;
            float w = (j < N_) ? adjb[i * N_ + j] : 0.f;
            unsigned bal = __ballot_sync(0xffffffffu, w > 0.f);
            if (lane == 0) smu[OFF_ADJB + i * 7 + c] = bal;   // pure adjacency bitset
            if ((i >> 5) == c) bal |= 1u << (i & 31);         // self-loop
            mw[c] = bal;
            float lg = NEGF;
            if ((bal >> lane) & 1u) lg = lrelu02(edi + sm[OFF_ES + j]);
            alr[c] = lg;
            mx = fmaxf(mx, lg);
        }
        mx = warpMax(mx);

        float s = 0.f;
        #pragma unroll
        for (int c = 0; c < 7; c++) {
            float e = __expf(alr[c] - mx);    // masked lanes underflow to 0
            al[c * 32 + lane] = e;            // in-bounds: row padded to 224
            s += e;
        }
        s = warpSum(s);
        const float inv = __fdividef(1.f, s);

        float acc0 = 0.f, acc1 = 0.f;
        #pragma unroll
        for (int c = 0; c < 7; c++) {
            unsigned w = mw[c];               // warp-uniform
            const float* hb = sm + OFF_H + c * 32 * D1_ + lane;
            const float* ab = al + c * 32;
            while (w) {
                const int t = __ffs(w) - 1; w &= w - 1;
                acc0 = fmaf(ab[t], hb[t * D1_], acc0);
                if (w) {
                    const int t2 = __ffs(w) - 1; w &= w - 1;
                    acc1 = fmaf(ab[t2], hb[t2 * D1_], acc1);
                }
            }
        }
        sm[OFF_HO + i * D1_ + lane] = (acc0 + acc1) * inv + b1_l;
    }
    __syncthreads();

    // ============ Phase C: pool-1 ===========================================
    {
        const float pw1_l = __ldg(&pw1[lane]);
        const float invn1 = __fdividef(1.f, sm[OFF_RED + 0]);
        for (int i0 = 0; i0 < N_; i0 += 8) {
            const int i = i0 + wid;
            float s = warpSum(sm[OFF_HO + i * D1_ + lane] * pw1_l);
            if (lane == 0) sm[OFF_SC + i] = __fdividef(1.f, 1.f + __expf(-s * invn1));
        }
    }
    __syncthreads();

    // stable descending rank == jax.lax.top_k order
    if (tid < N_) {
        const float si = sm[OFF_SC + tid];
        int cnt = 0;
        for (int j = 0; j < N_; j++) {
            const float sj = sm[OFF_SC + j];
            cnt += (sj > si) || (sj == si && j < tid);
        }
        if (cnt < K1_) smi[OFF_PERM + cnt] = tid;
    }
    __syncthreads();

    for (int r = tid; r < K1_; r += NT) {
        float v = sm[OFF_SC + smi[OFF_PERM + r]];
        sm[OFF_VAL + r] = v;
        out[512 * 2 + (size_t)b * K1_ + r] = v;
    }
    __syncthreads();

    // gated xk = hout[perm] * vals  (into dead h1 region)
    for (int t = tid; t < K1_ * D1_; t += NT) {
        const int r = t >> 5, d = t & 31;
        sm[OFF_H + t] = sm[OFF_HO + smi[OFF_PERM + r] * D1_ + d] * sm[OFF_VAL + r];
    }
    __syncthreads();

    // x1 readout (warp0)
    if (tid < 32) {
        float mx = -INFINITY, s = 0.f;
        for (int r = 0; r < K1_; r++) {
            float v = sm[OFF_H + r * D1_ + tid];
            mx = fmaxf(mx, v);
            s += v;
        }
        sm[OFF_Z + tid]      = mx;
        sm[OFF_Z + 32 + tid] = s * (1.f / K1_);
    }
    // AKB: pooled adjacency bitset from smem ADJB
    for (int t = tid; t < K1_ * 4; t += NT) {
        const int r = t >> 2, w = t & 3;
        const int pr = smi[OFF_PERM + r];
        unsigned bits = 0;
        const int cmax = min(w * 32 + 32, K1_);
        for (int c = w * 32; c < cmax; c++) {
            const int pc = smi[OFF_PERM + c];
            if ((smu[OFF_ADJB + pr * 7 + (pc >> 5)] >> (pc & 31)) & 1u)
                bits |= 1u << (c - w * 32);
        }
        smu[OFF_AKB + t] = bits;
    }
    __syncthreads();   // ADJB dead from here

    // a2 = ak | (ak_nz @ ak_nz)  (sparse bit iteration); stage W2 into ADJB
    for (int t = tid; t < K1_ * 4; t += NT) {
        const int r = t >> 2, w = t & 3;
        unsigned acc = smu[OFF_AKB + t];
        #pragma unroll
        for (int kc = 0; kc < 4; kc++) {
            unsigned rw = smu[OFF_AKB + r * 4 + kc];
            while (rw) {
                const int k = __ffs(rw) - 1; rw &= rw - 1;
                acc |= smu[OFF_AKB + (kc * 32 + k) * 4 + w];
            }
        }
        smu[OFF_A2B + t] = acc;
    }
    for (int t = tid; t < D1_ * D2_; t += NT) sm[OFF_ADJB + t] = W2[t];
    __syncthreads();

    // ============ Phase E: GAT2 =============================================
    const float a2s_l = __ldg(&a2s[lane]);
    const float a2d_l = __ldg(&a2d[lane]);
    const float b2_l  = __ldg(&b2[lane]);
    float* sXK   = sm + OFF_H;                 // [100x32] pooled features
    float* sH2   = sm + OFF_HO;                // [100x32]
    float* sOUT2 = sm + OFF_HO + K1_ * D2_;    // [100x32]
    float* sW2   = sm + OFF_ADJB;              // [32x32]
    float* sAL2  = sm + OFF_AL;                // [8x100] alpha scratch

    for (int i0 = 0; i0 < K1_; i0 += 8) {
        const int i = i0 + wid;
        if (i < K1_) {
            const float4* xr4 = (const float4*)(sXK + i * D1_);
            float acc = 0.f;
            #pragma unroll
            for (int k4 = 0; k4 < D1_ / 4; k4++) {
                float4 xv = xr4[k4];
                const int k = k4 * 4;
                acc = fmaf(xv.x, sW2[(k + 0) * D2_ + lane], acc);
                acc = fmaf(xv.y, sW2[(k + 1) * D2_ + lane], acc);
                acc = fmaf(xv.z, sW2[(k + 2) * D2_ + lane], acc);
                acc = fmaf(xv.w, sW2[(k + 3) * D2_ + lane], acc);
            }
            sH2[i * D2_ + lane] = acc;
            float es = warpSum(acc * a2s_l);
            float ed = warpSum(acc * a2d_l);
            if (lane == 0) { sm[OFF_ES + i] = es; sm[OFF_ED + i] = ed; }
        }
    }
    __syncthreads();

    for (int i0 = 0; i0 < K1_; i0 += 8) {
        const int i = i0 + wid;
        if (i < K1_) {
            const float edi = sm[OFF_ED + i];
            float* al2 = sAL2 + wid * K1_;
            float alr[4];
            float mx = -INFINITY;
            #pragma unroll
            for (int c = 0; c < 4; c++) {
                const int j = c * 32 + lane;
                float lg = NEGF;
                if (j < K1_) {
                    bool msk = (j == i) || ((smu[OFF_A2B + i * 4 + c] >> lane) & 1u);
                    if (msk) lg = lrelu02(edi + sm[OFF_ES + j]);
                }
                alr[c] = lg;
                mx = fmaxf(mx, lg);
            }
            mx = warpMax(mx);
            float sme = 0.f;
            #pragma unroll
            for (int c = 0; c < 4; c++) {
                const int j = c * 32 + lane;
                if (j < K1_) {
                    float e = __expf(alr[c] - mx);
                    al2[j] = e;
                    sme += e;
                }
            }
            sme = warpSum(sme);
            const float inv = __fdividef(1.f, sme);

            const float4* al4 = (const float4*)al2;
            float acc0 = 0.f, acc1 = 0.f, acc2 = 0.f, acc3 = 0.f;
            #pragma unroll 5
            for (int j4 = 0; j4 < K1_ / 4; j4++) {
                float4 a = al4[j4];
                const int j = j4 * 4;
                acc0 = fmaf(a.x, sH2[(j + 0) * D2_ + lane], acc0);
                acc1 = fmaf(a.y, sH2[(j + 1) * D2_ + lane], acc1);
                acc2 = fmaf(a.z, sH2[(j + 2) * D2_ + lane], acc2);
                acc3 = fmaf(a.w, sH2[(j + 3) * D2_ + lane], acc3);
            }
            sOUT2[i * D2_ + lane] = ((acc0 + acc1) + (acc2 + acc3)) * inv + b2_l;
        }
    }
    __syncthreads();

    // ============ Phase F: pool-2 ===========================================
    {
        const float pw2_l = __ldg(&pw2[lane]);
        const float invn2 = __fdividef(1.f, sm[OFF_RED + 1]);
        for (int i0 = 0; i0 < K1_; i0 += 8) {
            const int i = i0 + wid;
            if (i < K1_) {
                float s = warpSum(sOUT2[i * D2_ + lane] * pw2_l);
                if (lane == 0) sm[OFF_SC + i] = __fdividef(1.f, 1.f + __expf(-s * invn2));
            }
        }
    }
    __syncthreads();

    if (tid < K1_) {
        const float si = sm[OFF_SC + tid];
        int cnt = 0;
        for (int j = 0; j < K1_; j++) {
            const float sj = sm[OFF_SC + j];
            cnt += (sj > si) || (sj == si && j < tid);
        }
        if (cnt < K2_) smi[OFF_PERM2 + cnt] = tid;
    }
    __syncthreads();

    for (int r = tid; r < K2_; r += NT) {
        float v = sm[OFF_SC + smi[OFF_PERM2 + r]];
        sm[OFF_VAL + r] = v;
        out[512 * 2 + 512 * K1_ + (size_t)b * K2_ + r] = v;
    }
    __syncthreads();

    float* sXK2 = sm + OFF_H + K1_ * D1_;   // [50x32]
    for (int t = tid; t < K2_ * D2_; t += NT) {
        const int r = t >> 5, d = t & 31;
        sXK2[t] = sOUT2[smi[OFF_PERM2 + r] * D2_ + d] * sm[OFF_VAL + r];
    }
    __syncthreads();

    if (tid < 32) {
        float mx = -INFINITY, s = 0.f;
        for (int r = 0; r < K2_; r++) {
            float v = sXK2[r * D2_ + tid];
            mx = fmaxf(mx, v);
            s += v;
        }
        sm[OFF_Z + 64 + tid] = mx;
        sm[OFF_Z + 96 + tid] = s * (1.f / K2_);
    }
    __syncthreads();

    // ============ Phase G: MLP head (warp 0) ================================
    if (wid == 0) {
        const float invbn = 1.0f / sqrtf(1.0f + 1e-5f);
        float acc = __ldg(&fc1_b[lane]);
        #pragma unroll 4
        for (int k = 0; k < 128; k++) acc = fmaf(sm[OFF_Z + k], __ldg(&fc1_w[k * 32 + lane]), acc);
        acc = fmaxf(acc, 0.f);
        sm[OFF_Z + 128 + lane] = __ldg(&bn4_g[lane]) * acc * invbn + __ldg(&bn4_b[lane]);
        __syncwarp();
        if (lane < 8) {
            float a = __ldg(&fc2_b[lane]);
            #pragma unroll
            for (int k = 0; k < 32; k++) a = fmaf(sm[OFF_Z + 128 + k], __ldg(&fc2_w[k * 8 + lane]), a);
            a = fmaxf(a, 0.f);
            sm[OFF_Z + 160 + lane] = __ldg(&bn5_g[lane]) * a * invbn + __ldg(&bn5_b[lane]);
        }
        __syncwarp();
        if (lane < 2) {
            float a = __ldg(&fc3_b[lane]);
            #pragma unroll
            for (int k = 0; k < 8; k++) a = fmaf(sm[OFF_Z + 160 + k], __ldg(&fc3_w[k * 2 + lane]), a);
            sm[OFF_Z + 170 + lane] = a;
        }
        __syncwarp();
        if (lane == 0) {
            float l0 = sm[OFF_Z + 170], l1 = sm[OFF_Z + 171];
            float m = fmaxf(l0, l1);
            float lse = m + __logf(__expf(l0 - m) + __expf(l1 - m));
            out[(size_t)b * 2 + 0] = l0 - lse;
            out[(size_t)b * 2 + 1] = l1 - lse;
        }
    }
}

extern "C" void kernel_launch(void* const* d_in, const int* in_sizes, int n_in,
                              void* d_out, int out_size) {
    const float* x     = (const float*)d_in[0];
    const float* adj   = (const float*)d_in[1];
    const float* W1    = (const float*)d_in[2];
    const float* a1s   = (const float*)d_in[3];
    const float* a1d   = (const float*)d_in[4];
    const float* b1    = (const float*)d_in[5];
    const float* W2    = (const float*)d_in[6];
    const float* a2s   = (const float*)d_in[7];
    const float* a2d   = (const float*)d_in[8];
    const float* b2    = (const float*)d_in[9];
    const float* pw1   = (const float*)d_in[10];
    const float* pw2   = (const float*)d_in[11];
    const float* fc1w  = (const float*)d_in[12];
    const float* fc1b  = (const float*)d_in[13];
    const float* fc2w  = (const float*)d_in[14];
    const float* fc2b  = (const float*)d_in[15];
    const float* fc3w  = (const float*)d_in[16];
    const float* fc3b  = (const float*)d_in[17];
    const float* bn4g  = (const float*)d_in[18];
    const float* bn4b  = (const float*)d_in[19];
    const float* bn5g  = (const float*)d_in[20];
    const float* bn5b  = (const float*)d_in[21];
    float* out = (float*)d_out;

    const int smem_bytes = SMEM_FLOATS * (int)sizeof(float);
    cudaFuncSetAttribute(nngat_kernel, cudaFuncAttributeMaxDynamicSharedMemorySize,
                         smem_bytes);

    nngat_kernel<<<512, NT, smem_bytes>>>(
        x, adj, W1, a1s, a1d, b1, W2, a2s, a2d, b2, pw1, pw2,
        fc1w, fc1b, fc2w, fc2b, fc3w, fc3b, bn4g, bn4b, bn5g, bn5b, out);
}

// round 6
// speedup vs baseline: 1.4711x; 1.3544x over previous
#include <cuda_runtime.h>
#include <math.h>

// ---------------------------------------------------------------------------
// NNGAT_Net: B=512, N=200, INDIM=200.
// One CTA per batch, 512 threads (16 warps), 78.6KB smem => 2 CTAs/SM
// (32 warps/SM). Phase-B adjacency rows software-pipelined (prefetch i+16).
// W1 staged in dead HO region; W2 staged in dead ADJB region.
// Output: logp [512*2] | s1 [512*100] | s2 [512*50]
// ---------------------------------------------------------------------------

namespace {
constexpr int N_    = 200;
constexpr int IND   = 200;
constexpr int D1_   = 32;
constexpr int D2_   = 32;
constexpr int K1_   = 100;
constexpr int K2_   = 50;
constexpr int NT    = 512;          // 16 warps
constexpr int NW    = 16;
constexpr int ALP   = 224;          // padded alpha row (7*32)
constexpr float NEGF = -1e9f;

// shared memory layout (float indices)
constexpr int OFF_H     = 0;        // 6400: h1 [200x32]; later xk[100x32], xk2[50x32]@+3200
constexpr int OFF_HO    = 6400;     // 6400: W1 staged -> hout1 [200x32] -> sH2/sOUT2
constexpr int OFF_AL    = 12800;    // 3584: per-warp alpha rows [16x224]; readout scratch
constexpr int OFF_ES    = 16384;    // 200
constexpr int OFF_ED    = 16584;    // 200
constexpr int OFF_SC    = 16784;    // 200
constexpr int OFF_VAL   = 16984;    // 100
constexpr int OFF_PERM  = 17084;    // 100 (int)
constexpr int OFF_PERM2 = 17184;    // 52  (int)
constexpr int OFF_ADJB  = 17236;    // 1400 (u32): adj bitset [200][7]; later W2 [32x32]
constexpr int OFF_AKB   = 18636;    // 400 (u32)
constexpr int OFF_A2B   = 19036;    // 400 (u32)
constexpr int OFF_Z     = 19436;    // 192
constexpr int OFF_RED   = 19628;    // 32
constexpr int SMEM_FLOATS = 19660;  // 78640 bytes -> 2 CTAs/SM, 32 warps
}

__device__ __forceinline__ float warpMax(float v) {
    #pragma unroll
    for (int o = 16; o > 0; o >>= 1) v = fmaxf(v, __shfl_xor_sync(0xffffffffu, v, o));
    return v;
}
__device__ __forceinline__ float warpSum(float v) {
    #pragma unroll
    for (int o = 16; o > 0; o >>= 1) v += __shfl_xor_sync(0xffffffffu, v, o);
    return v;
}
__device__ __forceinline__ float lrelu02(float x) { return x > 0.f ? x : 0.2f * x; }

__global__ __launch_bounds__(NT, 2)
void nngat_kernel(
    const float* __restrict__ x,     const float* __restrict__ adj,
    const float* __restrict__ W1,    const float* __restrict__ a1s,
    const float* __restrict__ a1d,   const float* __restrict__ b1,
    const float* __restrict__ W2,    const float* __restrict__ a2s,
    const float* __restrict__ a2d,   const float* __restrict__ b2,
    const float* __restrict__ pw1,   const float* __restrict__ pw2,
    const float* __restrict__ fc1_w, const float* __restrict__ fc1_b,
    const float* __restrict__ fc2_w, const float* __restrict__ fc2_b,
    const float* __restrict__ fc3_w, const float* __restrict__ fc3_b,
    const float* __restrict__ bn4_g, const float* __restrict__ bn4_b,
    const float* __restrict__ bn5_g, const float* __restrict__ bn5_b,
    float* __restrict__ out)
{
    extern __shared__ float sm[];
    int*      smi = (int*)sm;
    unsigned* smu = (unsigned*)sm;

    const int b    = blockIdx.x;
    const int tid  = threadIdx.x;
    const int lane = tid & 31;
    const int wid  = tid >> 5;

    const float* xb   = x   + (size_t)b * N_ * IND;
    const float* adjb = adj + (size_t)b * N_ * N_;

    // ---- stage W1 into (currently dead) HO region; pw norms ----
    {
        const float4* w4 = (const float4*)W1;
        float4* d4 = (float4*)(sm + OFF_HO);
        for (int t = tid; t < IND * D1_ / 4; t += NT) d4[t] = w4[t];
    }
    if (wid == 0) {
        float v = pw1[lane];
        float s = warpSum(v * v);
        if (lane == 0) sm[OFF_RED + 0] = sqrtf(s) + 1e-16f;
    }
    if (wid == 1) {
        float v = pw2[lane];
        float s = warpSum(v * v);
        if (lane == 0) sm[OFF_RED + 1] = sqrtf(s) + 1e-16f;
    }
    __syncthreads();

    const float a1s_l = __ldg(&a1s[lane]);
    const float a1d_l = __ldg(&a1d[lane]);
    const float b1_l  = __ldg(&b1[lane]);

    // ============ Phase A: h = x @ W1 ; es/ed ===============================
    // 40 groups of 5 rows; warp takes groups wid, wid+16, wid+32.
    {
        const float* sW = sm + OFF_HO;
        for (int g = wid; g < 40; g += NW) {
            const int ib = g * 5;
            const float4* xp0 = (const float4*)(xb + (ib + 0) * IND);
            const float4* xp1 = (const float4*)(xb + (ib + 1) * IND);
            const float4* xp2 = (const float4*)(xb + (ib + 2) * IND);
            const float4* xp3 = (const float4*)(xb + (ib + 3) * IND);
            const float4* xp4 = (const float4*)(xb + (ib + 4) * IND);
            float a0 = 0.f, a1 = 0.f, a2 = 0.f, a3 = 0.f, a4 = 0.f;
            #pragma unroll 2
            for (int k4 = 0; k4 < IND / 4; k4++) {
                float4 v0 = __ldg(xp0 + k4);
                float4 v1 = __ldg(xp1 + k4);
                float4 v2 = __ldg(xp2 + k4);
                float4 v3 = __ldg(xp3 + k4);
                float4 v4 = __ldg(xp4 + k4);
                const int k = k4 * 4;
                float w0 = sW[(k + 0) * D1_ + lane];
                float w1 = sW[(k + 1) * D1_ + lane];
                float w2 = sW[(k + 2) * D1_ + lane];
                float w3 = sW[(k + 3) * D1_ + lane];
                a0 = fmaf(v0.x, w0, fmaf(v0.y, w1, fmaf(v0.z, w2, fmaf(v0.w, w3, a0))));
                a1 = fmaf(v1.x, w0, fmaf(v1.y, w1, fmaf(v1.z, w2, fmaf(v1.w, w3, a1))));
                a2 = fmaf(v2.x, w0, fmaf(v2.y, w1, fmaf(v2.z, w2, fmaf(v2.w, w3, a2))));
                a3 = fmaf(v3.x, w0, fmaf(v3.y, w1, fmaf(v3.z, w2, fmaf(v3.w, w3, a3))));
                a4 = fmaf(v4.x, w0, fmaf(v4.y, w1, fmaf(v4.z, w2, fmaf(v4.w, w3, a4))));
            }
            float hr[5] = {a0, a1, a2, a3, a4};
            #pragma unroll
            for (int r = 0; r < 5; r++) {
                sm[OFF_H + (ib + r) * D1_ + lane] = hr[r];
                float es = warpSum(hr[r] * a1s_l);
                float ed = warpSum(hr[r] * a1d_l);
                if (lane == 0) { sm[OFF_ES + ib + r] = es; sm[OFF_ED + ib + r] = ed; }
            }
        }
    }
    __syncthreads();   // W1 staging dead; HO becomes hout1

    // ============ Phase B: GAT1 softmax + sparse agg (pipelined adj) ========
    {
        float* al = sm + OFF_AL + wid * ALP;
        float wv[7];
        #pragma unroll
        for (int c = 0; c < 7; c++) {
            const int j = c * 32 + lane;
            wv[c] = (j < N_) ? adjb[wid * N_ + j] : 0.f;   // wid < 16 < 200
        }
        for (int i = wid; i < N_; i += NW) {
            // prefetch next row
            const int inext = i + NW;
            float wnx[7];
            if (inext < N_) {
                #pragma unroll
                for (int c = 0; c < 7; c++) {
                    const int j = c * 32 + lane;
                    wnx[c] = (j < N_) ? adjb[inext * N_ + j] : 0.f;
                }
            }

            const float edi = sm[OFF_ED + i];
            unsigned mw[7];
            float alr[7];
            float mx = -INFINITY;
            #pragma unroll
            for (int c = 0; c < 7; c++) {
                const int j = c * 32 + lane;
                unsigned bal = __ballot_sync(0xffffffffu, wv[c] > 0.f);
                if (lane == 0) smu[OFF_ADJB + i * 7 + c] = bal;  // pure adjacency
                if ((i >> 5) == c) bal |= 1u << (i & 31);        // self-loop
                mw[c] = bal;
                float lg = NEGF;
                if ((bal >> lane) & 1u) lg = lrelu02(edi + sm[OFF_ES + j]);
                alr[c] = lg;
                mx = fmaxf(mx, lg);
            }
            mx = warpMax(mx);

            float s = 0.f;
            #pragma unroll
            for (int c = 0; c < 7; c++) {
                float e = __expf(alr[c] - mx);    // masked lanes underflow to 0
                al[c * 32 + lane] = e;            // padded row: in-bounds
                s += e;
            }
            s = warpSum(s);
            const float inv = __fdividef(1.f, s);

            float acc0 = 0.f, acc1 = 0.f;
            #pragma unroll
            for (int c = 0; c < 7; c++) {
                unsigned w = mw[c];               // warp-uniform
                const float* hb = sm + OFF_H + c * 32 * D1_ + lane;
                const float* ab = al + c * 32;
                while (w) {
                    const int t = __ffs(w) - 1; w &= w - 1;
                    acc0 = fmaf(ab[t], hb[t * D1_], acc0);
                    if (w) {
                        const int t2 = __ffs(w) - 1; w &= w - 1;
                        acc1 = fmaf(ab[t2], hb[t2 * D1_], acc1);
                    }
                }
            }
            sm[OFF_HO + i * D1_ + lane] = (acc0 + acc1) * inv + b1_l;

            #pragma unroll
            for (int c = 0; c < 7; c++) wv[c] = wnx[c];
        }
    }
    __syncthreads();

    // ============ Phase C: pool-1 scores ====================================
    {
        const float pw1_l = __ldg(&pw1[lane]);
        const float invn1 = __fdividef(1.f, sm[OFF_RED + 0]);
        for (int i = wid; i < N_; i += NW) {
            float s = warpSum(sm[OFF_HO + i * D1_ + lane] * pw1_l);
            if (lane == 0) sm[OFF_SC + i] = __fdividef(1.f, 1.f + __expf(-s * invn1));
        }
    }
    __syncthreads();

    // stable descending rank == jax.lax.top_k order
    if (tid < N_) {
        const float si = sm[OFF_SC + tid];
        int cnt = 0;
        for (int j = 0; j < N_; j++) {
            const float sj = sm[OFF_SC + j];
            cnt += (sj > si) || (sj == si && j < tid);
        }
        if (cnt < K1_) smi[OFF_PERM + cnt] = tid;
    }
    __syncthreads();

    for (int r = tid; r < K1_; r += NT) {
        float v = sm[OFF_SC + smi[OFF_PERM + r]];
        sm[OFF_VAL + r] = v;
        out[512 * 2 + (size_t)b * K1_ + r] = v;
    }
    __syncthreads();

    // gated xk = hout[perm] * vals  (into dead h1 region)
    for (int t = tid; t < K1_ * D1_; t += NT) {
        const int r = t >> 5, d = t & 31;
        sm[OFF_H + t] = sm[OFF_HO + smi[OFF_PERM + r] * D1_ + d] * sm[OFF_VAL + r];
    }
    __syncthreads();

    // x1 readout partials (warps 0-3) + AKB build (all threads); AL is free
    if (wid < 4) {
        float mx = -INFINITY, s = 0.f;
        for (int r = wid * 25; r < wid * 25 + 25; r++) {
            float v = sm[OFF_H + r * D1_ + lane];
            mx = fmaxf(mx, v);
            s += v;
        }
        sm[OFF_AL + (wid * 2 + 0) * 32 + lane] = mx;
        sm[OFF_AL + (wid * 2 + 1) * 32 + lane] = s;
    }
    for (int t = tid; t < K1_ * 4; t += NT) {
        const int r = t >> 2, w = t & 3;
        const int pr = smi[OFF_PERM + r];
        unsigned bits = 0;
        const int cmax = min(w * 32 + 32, K1_);
        for (int c = w * 32; c < cmax; c++) {
            const int pc = smi[OFF_PERM + c];
            if ((smu[OFF_ADJB + pr * 7 + (pc >> 5)] >> (pc & 31)) & 1u)
                bits |= 1u << (c - w * 32);
        }
        smu[OFF_AKB + t] = bits;
    }
    __syncthreads();   // ADJB dead from here

    // combine x1 partials; a2 = ak | (ak_nz @ ak_nz); stage W2 into ADJB
    if (tid < 32) {
        float mx = fmaxf(fmaxf(sm[OFF_AL + 0 * 32 + lane], sm[OFF_AL + 2 * 32 + lane]),
                         fmaxf(sm[OFF_AL + 4 * 32 + lane], sm[OFF_AL + 6 * 32 + lane]));
        float s = sm[OFF_AL + 1 * 32 + lane] + sm[OFF_AL + 3 * 32 + lane]
                + sm[OFF_AL + 5 * 32 + lane] + sm[OFF_AL + 7 * 32 + lane];
        sm[OFF_Z + lane]      = mx;
        sm[OFF_Z + 32 + lane] = s * (1.f / K1_);
    }
    for (int t = tid; t < K1_ * 4; t += NT) {
        const int r = t >> 2, w = t & 3;
        unsigned acc = smu[OFF_AKB + t];
        #pragma unroll
        for (int kc = 0; kc < 4; kc++) {
            unsigned rw = smu[OFF_AKB + r * 4 + kc];
            while (rw) {
                const int k = __ffs(rw) - 1; rw &= rw - 1;
                acc |= smu[OFF_AKB + (kc * 32 + k) * 4 + w];
            }
        }
        smu[OFF_A2B + t] = acc;
    }
    for (int t = tid; t < D1_ * D2_; t += NT) sm[OFF_ADJB + t] = W2[t];
    __syncthreads();

    // ============ Phase E: GAT2 =============================================
    const float a2s_l = __ldg(&a2s[lane]);
    const float a2d_l = __ldg(&a2d[lane]);
    const float b2_l  = __ldg(&b2[lane]);
    float* sXK   = sm + OFF_H;                 // [100x32]
    float* sH2   = sm + OFF_HO;                // [100x32]
    float* sOUT2 = sm + OFF_HO + K1_ * D2_;    // [100x32]
    float* sW2   = sm + OFF_ADJB;              // [32x32]
    float* sAL2  = sm + OFF_AL;                // [16x100] alpha scratch

    for (int i = wid; i < K1_; i += NW) {
        const float4* xr4 = (const float4*)(sXK + i * D1_);
        float acc = 0.f;
        #pragma unroll
        for (int k4 = 0; k4 < D1_ / 4; k4++) {
            float4 xv = xr4[k4];
            const int k = k4 * 4;
            acc = fmaf(xv.x, sW2[(k + 0) * D2_ + lane], acc);
            acc = fmaf(xv.y, sW2[(k + 1) * D2_ + lane], acc);
            acc = fmaf(xv.z, sW2[(k + 2) * D2_ + lane], acc);
            acc = fmaf(xv.w, sW2[(k + 3) * D2_ + lane], acc);
        }
        sH2[i * D2_ + lane] = acc;
        float es = warpSum(acc * a2s_l);
        float ed = warpSum(acc * a2d_l);
        if (lane == 0) { sm[OFF_ES + i] = es; sm[OFF_ED + i] = ed; }
    }
    __syncthreads();

    for (int i = wid; i < K1_; i += NW) {
        const float edi = sm[OFF_ED + i];
        float* al2 = sAL2 + wid * K1_;
        float alr[4];
        float mx = -INFINITY;
        #pragma unroll
        for (int c = 0; c < 4; c++) {
            const int j = c * 32 + lane;
            float lg = NEGF;
            if (j < K1_) {
                bool msk = (j == i) || ((smu[OFF_A2B + i * 4 + c] >> lane) & 1u);
                if (msk) lg = lrelu02(edi + sm[OFF_ES + j]);
            }
            alr[c] = lg;
            mx = fmaxf(mx, lg);
        }
        mx = warpMax(mx);
        float sme = 0.f;
        #pragma unroll
        for (int c = 0; c < 4; c++) {
            const int j = c * 32 + lane;
            if (j < K1_) {
                float e = __expf(alr[c] - mx);
                al2[j] = e;
                sme += e;
            }
        }
        sme = warpSum(sme);
        const float inv = __fdividef(1.f, sme);

        const float4* al4 = (const float4*)al2;
        float acc0 = 0.f, acc1 = 0.f, acc2 = 0.f, acc3 = 0.f;
        #pragma unroll 5
        for (int j4 = 0; j4 < K1_ / 4; j4++) {
            float4 a = al4[j4];
            const int j = j4 * 4;
            acc0 = fmaf(a.x, sH2[(j + 0) * D2_ + lane], acc0);
            acc1 = fmaf(a.y, sH2[(j + 1) * D2_ + lane], acc1);
            acc2 = fmaf(a.z, sH2[(j + 2) * D2_ + lane], acc2);
            acc3 = fmaf(a.w, sH2[(j + 3) * D2_ + lane], acc3);
        }
        sOUT2[i * D2_ + lane] = ((acc0 + acc1) + (acc2 + acc3)) * inv + b2_l;
    }
    __syncthreads();

    // ============ Phase F: pool-2 ===========================================
    {
        const float pw2_l = __ldg(&pw2[lane]);
        const float invn2 = __fdividef(1.f, sm[OFF_RED + 1]);
        for (int i = wid; i < K1_; i += NW) {
            float s = warpSum(sOUT2[i * D2_ + lane] * pw2_l);
            if (lane == 0) sm[OFF_SC + i] = __fdividef(1.f, 1.f + __expf(-s * invn2));
        }
    }
    __syncthreads();

    if (tid < K1_) {
        const float si = sm[OFF_SC + tid];
        int cnt = 0;
        for (int j = 0; j < K1_; j++) {
            const float sj = sm[OFF_SC + j];
            cnt += (sj > si) || (sj == si && j < tid);
        }
        if (cnt < K2_) smi[OFF_PERM2 + cnt] = tid;
    }
    __syncthreads();

    for (int r = tid; r < K2_; r += NT) {
        float v = sm[OFF_SC + smi[OFF_PERM2 + r]];
        sm[OFF_VAL + r] = v;
        out[512 * 2 + 512 * K1_ + (size_t)b * K2_ + r] = v;
    }
    __syncthreads();

    float* sXK2 = sm + OFF_H + K1_ * D1_;   // [50x32]
    for (int t = tid; t < K2_ * D2_; t += NT) {
        const int r = t >> 5, d = t & 31;
        sXK2[t] = sOUT2[smi[OFF_PERM2 + r] * D2_ + d] * sm[OFF_VAL + r];
    }
    __syncthreads();

    // x2 readout partials (warps 0-1)
    if (wid < 2) {
        float mx = -INFINITY, s = 0.f;
        for (int r = wid * 25; r < wid * 25 + 25; r++) {
            float v = sXK2[r * D2_ + lane];
            mx = fmaxf(mx, v);
            s += v;
        }
        sm[OFF_AL + (wid * 2 + 0) * 32 + lane] = mx;
        sm[OFF_AL + (wid * 2 + 1) * 32 + lane] = s;
    }
    __syncthreads();
    if (tid < 32) {
        float mx = fmaxf(sm[OFF_AL + 0 * 32 + lane], sm[OFF_AL + 2 * 32 + lane]);
        float s  = sm[OFF_AL + 1 * 32 + lane] + sm[OFF_AL + 3 * 32 + lane];
        sm[OFF_Z + 64 + lane] = mx;
        sm[OFF_Z + 96 + lane] = s * (1.f / K2_);
    }
    __syncthreads();

    // ============ Phase G: MLP head (warp 0) ================================
    if (wid == 0) {
        const float invbn = 1.0f / sqrtf(1.0f + 1e-5f);
        float acc = __ldg(&fc1_b[lane]);
        #pragma unroll 4
        for (int k = 0; k < 128; k++) acc = fmaf(sm[OFF_Z + k], __ldg(&fc1_w[k * 32 + lane]), acc);
        acc = fmaxf(acc, 0.f);
        sm[OFF_Z + 128 + lane] = __ldg(&bn4_g[lane]) * acc * invbn + __ldg(&bn4_b[lane]);
        __syncwarp();
        if (lane < 8) {
            float a = __ldg(&fc2_b[lane]);
            #pragma unroll
            for (int k = 0; k < 32; k++) a = fmaf(sm[OFF_Z + 128 + k], __ldg(&fc2_w[k * 8 + lane]), a);
            a = fmaxf(a, 0.f);
            sm[OFF_Z + 160 + lane] = __ldg(&bn5_g[lane]) * a * invbn + __ldg(&bn5_b[lane]);
        }
        __syncwarp();
        if (lane < 2) {
            float a = __ldg(&fc3_b[lane]);
            #pragma unroll
            for (int k = 0; k < 8; k++) a = fmaf(sm[OFF_Z + 160 + k], __ldg(&fc3_w[k * 2 + lane]), a);
            sm[OFF_Z + 170 + lane] = a;
        }
        __syncwarp();
        if (lane == 0) {
            float l0 = sm[OFF_Z + 170], l1 = sm[OFF_Z + 171];
            float m = fmaxf(l0, l1);
            float lse = m + __logf(__expf(l0 - m) + __expf(l1 - m));
            out[(size_t)b * 2 + 0] = l0 - lse;
            out[(size_t)b * 2 + 1] = l1 - lse;
        }
    }
}

extern "C" void kernel_launch(void* const* d_in, const int* in_sizes, int n_in,
                              void* d_out, int out_size) {
    const float* x     = (const float*)d_in[0];
    const float* adj   = (const float*)d_in[1];
    const float* W1    = (const float*)d_in[2];
    const float* a1s   = (const float*)d_in[3];
    const float* a1d   = (const float*)d_in[4];
    const float* b1    = (const float*)d_in[5];
    const float* W2    = (const float*)d_in[6];
    const float* a2s   = (const float*)d_in[7];
    const float* a2d   = (const float*)d_in[8];
    const float* b2    = (const float*)d_in[9];
    const float* pw1   = (const float*)d_in[10];
    const float* pw2   = (const float*)d_in[11];
    const float* fc1w  = (const float*)d_in[12];
    const float* fc1b  = (const float*)d_in[13];
    const float* fc2w  = (const float*)d_in[14];
    const float* fc2b  = (const float*)d_in[15];
    const float* fc3w  = (const float*)d_in[16];
    const float* fc3b  = (const float*)d_in[17];
    const float* bn4g  = (const float*)d_in[18];
    const float* bn4b  = (const float*)d_in[19];
    const float* bn5g  = (const float*)d_in[20];
    const float* bn5b  = (const float*)d_in[21];
    float* out = (float*)d_out;

    const int smem_bytes = SMEM_FLOATS * (int)sizeof(float);
    cudaFuncSetAttribute(nngat_kernel, cudaFuncAttributeMaxDynamicSharedMemorySize,
                         smem_bytes);

    nngat_kernel<<<512, NT, smem_bytes>>>(
        x, adj, W1, a1s, a1d, b1, W2, a2s, a2d, b2, pw1, pw2,
        fc1w, fc1b, fc2w, fc2b, fc3w, fc3b, bn4g, bn4b, bn5g, bn5b, out);
}

// round 7
// speedup vs baseline: 1.5568x; 1.0582x over previous
#include <cuda_runtime.h>
#include <math.h>

// ---------------------------------------------------------------------------
// NNGAT_Net: B=512, N=200, INDIM=200.
// One CTA per batch, 512 threads (16 warps), 78.6KB smem => 2 CTAs/SM.
// R7: AKB built via warp ballot (kills ~25k LDS/CTA); GAT2 aggregation 2 rows
// per warp (halves h2 LDS, 8 FMA chains); Phase-B 4-wide bit extraction.
// Output: logp [512*2] | s1 [512*100] | s2 [512*50]
// ---------------------------------------------------------------------------

namespace {
constexpr int N_    = 200;
constexpr int IND   = 200;
constexpr int D1_   = 32;
constexpr int D2_   = 32;
constexpr int K1_   = 100;
constexpr int K2_   = 50;
constexpr int NT    = 512;          // 16 warps
constexpr int NW    = 16;
constexpr int ALP   = 224;          // padded alpha row (7*32)
constexpr float NEGF = -1e9f;

// shared memory layout (float indices)
constexpr int OFF_H     = 0;        // 6400: h1 [200x32]; later xk[100x32], xk2[50x32]@+3200
constexpr int OFF_HO    = 6400;     // 6400: W1 staged -> hout1 [200x32] -> sH2/sOUT2
constexpr int OFF_AL    = 12800;    // 3584: per-warp alpha rows [16x224]; readout scratch
constexpr int OFF_ES    = 16384;    // 200
constexpr int OFF_ED    = 16584;    // 200
constexpr int OFF_SC    = 16784;    // 200
constexpr int OFF_VAL   = 16984;    // 100
constexpr int OFF_PERM  = 17084;    // 100 (int)
constexpr int OFF_PERM2 = 17184;    // 52  (int)
constexpr int OFF_ADJB  = 17236;    // 1400 (u32): adj bitset [200][7]; later W2 [32x32]
constexpr int OFF_AKB   = 18636;    // 400 (u32)
constexpr int OFF_A2B   = 19036;    // 400 (u32)
constexpr int OFF_Z     = 19436;    // 192
constexpr int OFF_RED   = 19628;    // 32
constexpr int SMEM_FLOATS = 19660;  // 78640 bytes -> 2 CTAs/SM, 32 warps
}

__device__ __forceinline__ float warpMax(float v) {
    #pragma unroll
    for (int o = 16; o > 0; o >>= 1) v = fmaxf(v, __shfl_xor_sync(0xffffffffu, v, o));
    return v;
}
__device__ __forceinline__ float warpSum(float v) {
    #pragma unroll
    for (int o = 16; o > 0; o >>= 1) v += __shfl_xor_sync(0xffffffffu, v, o);
    return v;
}
__device__ __forceinline__ float lrelu02(float x) { return x > 0.f ? x : 0.2f * x; }

__global__ __launch_bounds__(NT, 2)
void nngat_kernel(
    const float* __restrict__ x,     const float* __restrict__ adj,
    const float* __restrict__ W1,    const float* __restrict__ a1s,
    const float* __restrict__ a1d,   const float* __restrict__ b1,
    const float* __restrict__ W2,    const float* __restrict__ a2s,
    const float* __restrict__ a2d,   const float* __restrict__ b2,
    const float* __restrict__ pw1,   const float* __restrict__ pw2,
    const float* __restrict__ fc1_w, const float* __restrict__ fc1_b,
    const float* __restrict__ fc2_w, const float* __restrict__ fc2_b,
    const float* __restrict__ fc3_w, const float* __restrict__ fc3_b,
    const float* __restrict__ bn4_g, const float* __restrict__ bn4_b,
    const float* __restrict__ bn5_g, const float* __restrict__ bn5_b,
    float* __restrict__ out)
{
    extern __shared__ float sm[];
    int*      smi = (int*)sm;
    unsigned* smu = (unsigned*)sm;

    const int b    = blockIdx.x;
    const int tid  = threadIdx.x;
    const int lane = tid & 31;
    const int wid  = tid >> 5;

    const float* xb   = x   + (size_t)b * N_ * IND;
    const float* adjb = adj + (size_t)b * N_ * N_;

    // ---- stage W1 into (currently dead) HO region; pw norms ----
    {
        const float4* w4 = (const float4*)W1;
        float4* d4 = (float4*)(sm + OFF_HO);
        for (int t = tid; t < IND * D1_ / 4; t += NT) d4[t] = w4[t];
    }
    if (wid == 0) {
        float v = pw1[lane];
        float s = warpSum(v * v);
        if (lane == 0) sm[OFF_RED + 0] = sqrtf(s) + 1e-16f;
    }
    if (wid == 1) {
        float v = pw2[lane];
        float s = warpSum(v * v);
        if (lane == 0) sm[OFF_RED + 1] = sqrtf(s) + 1e-16f;
    }
    __syncthreads();

    const float a1s_l = __ldg(&a1s[lane]);
    const float a1d_l = __ldg(&a1d[lane]);
    const float b1_l  = __ldg(&b1[lane]);

    // ============ Phase A: h = x @ W1 ; es/ed ===============================
    {
        const float* sW = sm + OFF_HO;
        for (int g = wid; g < 40; g += NW) {
            const int ib = g * 5;
            const float4* xp0 = (const float4*)(xb + (ib + 0) * IND);
            const float4* xp1 = (const float4*)(xb + (ib + 1) * IND);
            const float4* xp2 = (const float4*)(xb + (ib + 2) * IND);
            const float4* xp3 = (const float4*)(xb + (ib + 3) * IND);
            const float4* xp4 = (const float4*)(xb + (ib + 4) * IND);
            float a0 = 0.f, a1 = 0.f, a2 = 0.f, a3 = 0.f, a4 = 0.f;
            #pragma unroll 2
            for (int k4 = 0; k4 < IND / 4; k4++) {
                float4 v0 = __ldg(xp0 + k4);
                float4 v1 = __ldg(xp1 + k4);
                float4 v2 = __ldg(xp2 + k4);
                float4 v3 = __ldg(xp3 + k4);
                float4 v4 = __ldg(xp4 + k4);
                const int k = k4 * 4;
                float w0 = sW[(k + 0) * D1_ + lane];
                float w1 = sW[(k + 1) * D1_ + lane];
                float w2 = sW[(k + 2) * D1_ + lane];
                float w3 = sW[(k + 3) * D1_ + lane];
                a0 = fmaf(v0.x, w0, fmaf(v0.y, w1, fmaf(v0.z, w2, fmaf(v0.w, w3, a0))));
                a1 = fmaf(v1.x, w0, fmaf(v1.y, w1, fmaf(v1.z, w2, fmaf(v1.w, w3, a1))));
                a2 = fmaf(v2.x, w0, fmaf(v2.y, w1, fmaf(v2.z, w2, fmaf(v2.w, w3, a2))));
                a3 = fmaf(v3.x, w0, fmaf(v3.y, w1, fmaf(v3.z, w2, fmaf(v3.w, w3, a3))));
                a4 = fmaf(v4.x, w0, fmaf(v4.y, w1, fmaf(v4.z, w2, fmaf(v4.w, w3, a4))));
            }
            float hr[5] = {a0, a1, a2, a3, a4};
            #pragma unroll
            for (int r = 0; r < 5; r++) {
                sm[OFF_H + (ib + r) * D1_ + lane] = hr[r];
                float es = warpSum(hr[r] * a1s_l);
                float ed = warpSum(hr[r] * a1d_l);
                if (lane == 0) { sm[OFF_ES + ib + r] = es; sm[OFF_ED + ib + r] = ed; }
            }
        }
    }
    __syncthreads();   // W1 staging dead; HO becomes hout1

    // ============ Phase B: GAT1 softmax + sparse agg (pipelined adj) ========
    {
        float* al = sm + OFF_AL + wid * ALP;
        float wv[7];
        #pragma unroll
        for (int c = 0; c < 7; c++) {
            const int j = c * 32 + lane;
            wv[c] = (j < N_) ? adjb[wid * N_ + j] : 0.f;   // wid < 16 < 200
        }
        for (int i = wid; i < N_; i += NW) {
            const int inext = i + NW;
            float wnx[7];
            if (inext < N_) {
                #pragma unroll
                for (int c = 0; c < 7; c++) {
                    const int j = c * 32 + lane;
                    wnx[c] = (j < N_) ? adjb[inext * N_ + j] : 0.f;
                }
            }

            const float edi = sm[OFF_ED + i];
            unsigned mw[7];
            float alr[7];
            float mx = -INFINITY;
            #pragma unroll
            for (int c = 0; c < 7; c++) {
                const int j = c * 32 + lane;
                unsigned bal = __ballot_sync(0xffffffffu, wv[c] > 0.f);
                if (lane == 0) smu[OFF_ADJB + i * 7 + c] = bal;  // pure adjacency
                if ((i >> 5) == c) bal |= 1u << (i & 31);        // self-loop
                mw[c] = bal;
                float lg = NEGF;
                if ((bal >> lane) & 1u) lg = lrelu02(edi + sm[OFF_ES + j]);
                alr[c] = lg;
                mx = fmaxf(mx, lg);
            }
            mx = warpMax(mx);

            float s = 0.f;
            #pragma unroll
            for (int c = 0; c < 7; c++) {
                float e = __expf(alr[c] - mx);    // masked lanes underflow to 0
                al[c * 32 + lane] = e;            // padded row: in-bounds
                s += e;
            }
            s = warpSum(s);
            const float inv = __fdividef(1.f, s);

            float acc0 = 0.f, acc1 = 0.f, acc2 = 0.f, acc3 = 0.f;
            #pragma unroll
            for (int c = 0; c < 7; c++) {
                unsigned w = mw[c];               // warp-uniform
                const float* hb = sm + OFF_H + c * 32 * D1_ + lane;
                const float* ab = al + c * 32;
                while (w) {
                    const int t0 = __ffs(w) - 1; w &= w - 1;
                    acc0 = fmaf(ab[t0], hb[t0 * D1_], acc0);
                    if (!w) break;
                    const int t1 = __ffs(w) - 1; w &= w - 1;
                    acc1 = fmaf(ab[t1], hb[t1 * D1_], acc1);
                    if (!w) break;
                    const int t2 = __ffs(w) - 1; w &= w - 1;
                    acc2 = fmaf(ab[t2], hb[t2 * D1_], acc2);
                    if (!w) break;
                    const int t3 = __ffs(w) - 1; w &= w - 1;
                    acc3 = fmaf(ab[t3], hb[t3 * D1_], acc3);
                }
            }
            sm[OFF_HO + i * D1_ + lane] = ((acc0 + acc1) + (acc2 + acc3)) * inv + b1_l;

            #pragma unroll
            for (int c = 0; c < 7; c++) wv[c] = wnx[c];
        }
    }
    __syncthreads();

    // ============ Phase C: pool-1 scores ====================================
    {
        const float pw1_l = __ldg(&pw1[lane]);
        const float invn1 = __fdividef(1.f, sm[OFF_RED + 0]);
        for (int i = wid; i < N_; i += NW) {
            float s = warpSum(sm[OFF_HO + i * D1_ + lane] * pw1_l);
            if (lane == 0) sm[OFF_SC + i] = __fdividef(1.f, 1.f + __expf(-s * invn1));
        }
    }
    __syncthreads();

    // stable descending rank == jax.lax.top_k order
    if (tid < N_) {
        const float si = sm[OFF_SC + tid];
        int cnt = 0;
        for (int j = 0; j < N_; j++) {
            const float sj = sm[OFF_SC + j];
            cnt += (sj > si) || (sj == si && j < tid);
        }
        if (cnt < K1_) smi[OFF_PERM + cnt] = tid;
    }
    __syncthreads();

    for (int r = tid; r < K1_; r += NT) {
        float v = sm[OFF_SC + smi[OFF_PERM + r]];
        sm[OFF_VAL + r] = v;
        out[512 * 2 + (size_t)b * K1_ + r] = v;
    }
    __syncthreads();

    // gated xk = hout[perm] * vals  (into dead h1 region)
    for (int t = tid; t < K1_ * D1_; t += NT) {
        const int r = t >> 5, d = t & 31;
        sm[OFF_H + t] = sm[OFF_HO + smi[OFF_PERM + r] * D1_ + d] * sm[OFF_VAL + r];
    }
    __syncthreads();

    // x1 readout partials (warps 0-3)
    if (wid < 4) {
        float mx = -INFINITY, s = 0.f;
        for (int r = wid * 25; r < wid * 25 + 25; r++) {
            float v = sm[OFF_H + r * D1_ + lane];
            mx = fmaxf(mx, v);
            s += v;
        }
        sm[OFF_AL + (wid * 2 + 0) * 32 + lane] = mx;
        sm[OFF_AL + (wid * 2 + 1) * 32 + lane] = s;
    }
    // AKB via warp ballot: lane = pooled column
    for (int r = wid; r < K1_; r += NW) {
        const int pr = smi[OFF_PERM + r];
        const unsigned* arow = smu + OFF_ADJB + pr * 7;
        #pragma unroll
        for (int w = 0; w < 4; w++) {
            const int c = w * 32 + lane;
            bool bit = false;
            if (c < K1_) {
                const int pc = smi[OFF_PERM + c];
                bit = (arow[pc >> 5] >> (pc & 31)) & 1u;
            }
            unsigned bal = __ballot_sync(0xffffffffu, bit);
            if (lane == 0) smu[OFF_AKB + r * 4 + w] = bal;
        }
    }
    __syncthreads();   // ADJB dead from here

    // combine x1 partials; a2 = ak | (ak_nz @ ak_nz); stage W2 into ADJB
    if (tid < 32) {
        float mx = fmaxf(fmaxf(sm[OFF_AL + 0 * 32 + lane], sm[OFF_AL + 2 * 32 + lane]),
                         fmaxf(sm[OFF_AL + 4 * 32 + lane], sm[OFF_AL + 6 * 32 + lane]));
        float s = sm[OFF_AL + 1 * 32 + lane] + sm[OFF_AL + 3 * 32 + lane]
                + sm[OFF_AL + 5 * 32 + lane] + sm[OFF_AL + 7 * 32 + lane];
        sm[OFF_Z + lane]      = mx;
        sm[OFF_Z + 32 + lane] = s * (1.f / K1_);
    }
    for (int t = tid; t < K1_ * 4; t += NT) {
        const int r = t >> 2, w = t & 3;
        unsigned acc = smu[OFF_AKB + t];
        #pragma unroll
        for (int kc = 0; kc < 4; kc++) {
            unsigned rw = smu[OFF_AKB + r * 4 + kc];
            while (rw) {
                const int k = __ffs(rw) - 1; rw &= rw - 1;
                acc |= smu[OFF_AKB + (kc * 32 + k) * 4 + w];
            }
        }
        smu[OFF_A2B + t] = acc;
    }
    for (int t = tid; t < D1_ * D2_; t += NT) sm[OFF_ADJB + t] = W2[t];
    __syncthreads();

    // ============ Phase E: GAT2 =============================================
    const float a2s_l = __ldg(&a2s[lane]);
    const float a2d_l = __ldg(&a2d[lane]);
    const float b2_l  = __ldg(&b2[lane]);
    float* sXK   = sm + OFF_H;                 // [100x32]
    float* sH2   = sm + OFF_HO;                // [100x32]
    float* sOUT2 = sm + OFF_HO + K1_ * D2_;    // [100x32]
    float* sW2   = sm + OFF_ADJB;              // [32x32]
    float* sAL2  = sm + OFF_AL;                // [16 x ALP] alpha scratch

    for (int i = wid; i < K1_; i += NW) {
        const float4* xr4 = (const float4*)(sXK + i * D1_);
        float acc = 0.f;
        #pragma unroll
        for (int k4 = 0; k4 < D1_ / 4; k4++) {
            float4 xv = xr4[k4];
            const int k = k4 * 4;
            acc = fmaf(xv.x, sW2[(k + 0) * D2_ + lane], acc);
            acc = fmaf(xv.y, sW2[(k + 1) * D2_ + lane], acc);
            acc = fmaf(xv.z, sW2[(k + 2) * D2_ + lane], acc);
            acc = fmaf(xv.w, sW2[(k + 3) * D2_ + lane], acc);
        }
        sH2[i * D2_ + lane] = acc;
        float es = warpSum(acc * a2s_l);
        float ed = warpSum(acc * a2d_l);
        if (lane == 0) { sm[OFF_ES + i] = es; sm[OFF_ED + i] = ed; }
    }
    __syncthreads();

    // GAT2 attention + aggregation: 2 rows per warp
    for (int g = wid; g < K1_ / 2; g += NW) {
        const int i0 = 2 * g, i1 = i0 + 1;
        const float ed0 = sm[OFF_ED + i0];
        const float ed1 = sm[OFF_ED + i1];
        float* al2 = sAL2 + wid * ALP;
        float alr0[4], alr1[4];
        float mx0 = -INFINITY, mx1 = -INFINITY;
        #pragma unroll
        for (int c = 0; c < 4; c++) {
            const int j = c * 32 + lane;
            float lg0 = NEGF, lg1 = NEGF;
            if (j < K1_) {
                const float esj = sm[OFF_ES + j];
                const unsigned b0 = smu[OFF_A2B + i0 * 4 + c];
                const unsigned b1w = smu[OFF_A2B + i1 * 4 + c];
                if ((j == i0) || ((b0 >> lane) & 1u))  lg0 = lrelu02(ed0 + esj);
                if ((j == i1) || ((b1w >> lane) & 1u)) lg1 = lrelu02(ed1 + esj);
            }
            alr0[c] = lg0; alr1[c] = lg1;
            mx0 = fmaxf(mx0, lg0); mx1 = fmaxf(mx1, lg1);
        }
        mx0 = warpMax(mx0); mx1 = warpMax(mx1);
        float s0 = 0.f, s1 = 0.f;
        #pragma unroll
        for (int c = 0; c < 4; c++) {
            const int j = c * 32 + lane;
            if (j < K1_) {
                float e0 = __expf(alr0[c] - mx0);
                float e1 = __expf(alr1[c] - mx1);
                al2[j] = e0;
                al2[100 + j] = e1;
                s0 += e0; s1 += e1;
            }
        }
        s0 = warpSum(s0); s1 = warpSum(s1);
        const float inv0 = __fdividef(1.f, s0);
        const float inv1 = __fdividef(1.f, s1);

        const float4* a40 = (const float4*)al2;
        const float4* a41 = (const float4*)(al2 + 100);
        float p00 = 0.f, p01 = 0.f, p02 = 0.f, p03 = 0.f;
        float p10 = 0.f, p11 = 0.f, p12 = 0.f, p13 = 0.f;
        #pragma unroll 5
        for (int j4 = 0; j4 < K1_ / 4; j4++) {
            float4 a0 = a40[j4];
            float4 a1 = a41[j4];
            const int j = j4 * 4;
            float h0 = sH2[(j + 0) * D2_ + lane];
            float h1 = sH2[(j + 1) * D2_ + lane];
            float h2 = sH2[(j + 2) * D2_ + lane];
            float h3 = sH2[(j + 3) * D2_ + lane];
            p00 = fmaf(a0.x, h0, p00); p01 = fmaf(a0.y, h1, p01);
            p02 = fmaf(a0.z, h2, p02); p03 = fmaf(a0.w, h3, p03);
            p10 = fmaf(a1.x, h0, p10); p11 = fmaf(a1.y, h1, p11);
            p12 = fmaf(a1.z, h2, p12); p13 = fmaf(a1.w, h3, p13);
        }
        sOUT2[i0 * D2_ + lane] = ((p00 + p01) + (p02 + p03)) * inv0 + b2_l;
        sOUT2[i1 * D2_ + lane] = ((p10 + p11) + (p12 + p13)) * inv1 + b2_l;
    }
    __syncthreads();

    // ============ Phase F: pool-2 ===========================================
    {
        const float pw2_l = __ldg(&pw2[lane]);
        const float invn2 = __fdividef(1.f, sm[OFF_RED + 1]);
        for (int i = wid; i < K1_; i += NW) {
            float s = warpSum(sOUT2[i * D2_ + lane] * pw2_l);
            if (lane == 0) sm[OFF_SC + i] = __fdividef(1.f, 1.f + __expf(-s * invn2));
        }
    }
    __syncthreads();

    if (tid < K1_) {
        const float si = sm[OFF_SC + tid];
        int cnt = 0;
        for (int j = 0; j < K1_; j++) {
            const float sj = sm[OFF_SC + j];
            cnt += (sj > si) || (sj == si && j < tid);
        }
        if (cnt < K2_) smi[OFF_PERM2 + cnt] = tid;
    }
    __syncthreads();

    for (int r = tid; r < K2_; r += NT) {
        float v = sm[OFF_SC + smi[OFF_PERM2 + r]];
        sm[OFF_VAL + r] = v;
        out[512 * 2 + 512 * K1_ + (size_t)b * K2_ + r] = v;
    }
    __syncthreads();

    float* sXK2 = sm + OFF_H + K1_ * D1_;   // [50x32]
    for (int t = tid; t < K2_ * D2_; t += NT) {
        const int r = t >> 5, d = t & 31;
        sXK2[t] = sOUT2[smi[OFF_PERM2 + r] * D2_ + d] * sm[OFF_VAL + r];
    }
    __syncthreads();

    // x2 readout partials (warps 0-1)
    if (wid < 2) {
        float mx = -INFINITY, s = 0.f;
        for (int r = wid * 25; r < wid * 25 + 25; r++) {
            float v = sXK2[r * D2_ + lane];
            mx = fmaxf(mx, v);
            s += v;
        }
        sm[OFF_AL + (wid * 2 + 0) * 32 + lane] = mx;
        sm[OFF_AL + (wid * 2 + 1) * 32 + lane] = s;
    }
    __syncthreads();
    if (tid < 32) {
        float mx = fmaxf(sm[OFF_AL + 0 * 32 + lane], sm[OFF_AL + 2 * 32 + lane]);
        float s  = sm[OFF_AL + 1 * 32 + lane] + sm[OFF_AL + 3 * 32 + lane];
        sm[OFF_Z + 64 + lane] = mx;
        sm[OFF_Z + 96 + lane] = s * (1.f / K2_);
    }
    __syncthreads();

    // ============ Phase G: MLP head (warp 0) ================================
    if (wid == 0) {
        const float invbn = 1.0f / sqrtf(1.0f + 1e-5f);
        float acc = __ldg(&fc1_b[lane]);
        #pragma unroll 4
        for (int k = 0; k < 128; k++) acc = fmaf(sm[OFF_Z + k], __ldg(&fc1_w[k * 32 + lane]), acc);
        acc = fmaxf(acc, 0.f);
        sm[OFF_Z + 128 + lane] = __ldg(&bn4_g[lane]) * acc * invbn + __ldg(&bn4_b[lane]);
        __syncwarp();
        if (lane < 8) {
            float a = __ldg(&fc2_b[lane]);
            #pragma unroll
            for (int k = 0; k < 32; k++) a = fmaf(sm[OFF_Z + 128 + k], __ldg(&fc2_w[k * 8 + lane]), a);
            a = fmaxf(a, 0.f);
            sm[OFF_Z + 160 + lane] = __ldg(&bn5_g[lane]) * a * invbn + __ldg(&bn5_b[lane]);
        }
        __syncwarp();
        if (lane < 2) {
            float a = __ldg(&fc3_b[lane]);
            #pragma unroll
            for (int k = 0; k < 8; k++) a = fmaf(sm[OFF_Z + 160 + k], __ldg(&fc3_w[k * 2 + lane]), a);
            sm[OFF_Z + 170 + lane] = a;
        }
        __syncwarp();
        if (lane == 0) {
            float l0 = sm[OFF_Z + 170], l1 = sm[OFF_Z + 171];
            float m = fmaxf(l0, l1);
            float lse = m + __logf(__expf(l0 - m) + __expf(l1 - m));
            out[(size_t)b * 2 + 0] = l0 - lse;
            out[(size_t)b * 2 + 1] = l1 - lse;
        }
    }
}

extern "C" void kernel_launch(void* const* d_in, const int* in_sizes, int n_in,
                              void* d_out, int out_size) {
    const float* x     = (const float*)d_in[0];
    const float* adj   = (const float*)d_in[1];
    const float* W1    = (const float*)d_in[2];
    const float* a1s   = (const float*)d_in[3];
    const float* a1d   = (const float*)d_in[4];
    const float* b1    = (const float*)d_in[5];
    const float* W2    = (const float*)d_in[6];
    const float* a2s   = (const float*)d_in[7];
    const float* a2d   = (const float*)d_in[8];
    const float* b2    = (const float*)d_in[9];
    const float* pw1   = (const float*)d_in[10];
    const float* pw2   = (const float*)d_in[11];
    const float* fc1w  = (const float*)d_in[12];
    const float* fc1b  = (const float*)d_in[13];
    const float* fc2w  = (const float*)d_in[14];
    const float* fc2b  = (const float*)d_in[15];
    const float* fc3w  = (const float*)d_in[16];
    const float* fc3b  = (const float*)d_in[17];
    const float* bn4g  = (const float*)d_in[18];
    const float* bn4b  = (const float*)d_in[19];
    const float* bn5g  = (const float*)d_in[20];
    const float* bn5b  = (const float*)d_in[21];
    float* out = (float*)d_out;

    const int smem_bytes = SMEM_FLOATS * (int)sizeof(float);
    cudaFuncSetAttribute(nngat_kernel, cudaFuncAttributeMaxDynamicSharedMemorySize,
                         smem_bytes);

    nngat_kernel<<<512, NT, smem_bytes>>>(
        x, adj, W1, a1s, a1d, b1, W2, a2s, a2d, b2, pw1, pw2,
        fc1w, fc1b, fc2w, fc2b, fc3w, fc3b, bn4g, bn4b, bn5g, bn5b, out);
}